// round 2
// baseline (speedup 1.0000x reference)
#include <cuda_runtime.h>
#include <math.h>

#define TT 16
#define NN 128
#define FF 128
#define TN (TT*NN)

// ---- scratch (__device__ globals; no allocation allowed) ----
__device__ float g_aggr[TT*NN*FF];
__device__ float g_y[TT*NN*FF];
__device__ float g_node1[TT*NN*FF];
__device__ float g_node2[TT*NN*FF];
__device__ float g_sum[FF];
__device__ float g_sumsq[FF];
__device__ float g_nrm[TT*NN];

__device__ __forceinline__ float my_tanh(float x) {
    // tanh(x) = 1 - 2/(exp(2x)+1); __expf -> MUFU.EX2, __fdividef -> MUFU.RCP
    float e = __expf(2.0f * x);
    return 1.0f - __fdividef(2.0f, e + 1.0f);
}
__device__ __forceinline__ float lrelu(float v) { return v >= 0.0f ? v : 0.01f * v; }

// ---- row norms: grid=T, block=128 (thread n sums its own row) ----
__global__ void k_norms(const float* __restrict__ x) {
    int t = blockIdx.x, n = threadIdx.x;
    const float* row = x + (t * NN + n) * FF;
    float s = 0.0f;
#pragma unroll 8
    for (int f = 0; f < FF; ++f) { float v = row[f]; s = fmaf(v, v, s); }
    g_nrm[t * NN + n] = sqrtf(s);
}

// ---- sim_cal: grid=(16 tiles, T), 256 threads, 2x2 register tile per thread ----
__global__ void k_simcal(const float* __restrict__ x, float* __restrict__ out) {
    __shared__ float As[32][33], Bs[32][33];
    __shared__ float nA[32], nB[32];
    int t = blockIdx.y;
    int nt = blockIdx.x >> 2, mt = blockIdx.x & 3;
    int tid = threadIdx.x;
    if (tid < 32)       nA[tid]      = g_nrm[t * NN + nt * 32 + tid];
    else if (tid < 64)  nB[tid - 32] = g_nrm[t * NN + mt * 32 + (tid - 32)];
    int rt = tid & 15, ct = tid >> 4;
    float a00 = 0.f, a01 = 0.f, a10 = 0.f, a11 = 0.f;
    for (int fc = 0; fc < FF; fc += 32) {
        __syncthreads();
        int rr = tid >> 5, cc = tid & 31;
#pragma unroll
        for (int k = 0; k < 4; ++k) {
            As[rr + k * 8][cc] = x[(t * NN + nt * 32 + rr + k * 8) * FF + fc + cc];
            Bs[rr + k * 8][cc] = x[(t * NN + mt * 32 + rr + k * 8) * FF + fc + cc];
        }
        __syncthreads();
#pragma unroll
        for (int ff = 0; ff < 32; ++ff) {
            float r0 = As[rt * 2][ff], r1 = As[rt * 2 + 1][ff];
            float c0 = Bs[ct * 2][ff], c1 = Bs[ct * 2 + 1][ff];
            a00 = fmaf(r0, c0, a00); a01 = fmaf(r0, c1, a01);
            a10 = fmaf(r1, c0, a10); a11 = fmaf(r1, c1, a11);
        }
    }
    float acc[2][2] = { {a00, a01}, {a10, a11} };
#pragma unroll
    for (int k = 0; k < 2; ++k) {
#pragma unroll
        for (int q = 0; q < 2; ++q) {
            int n = nt * 32 + rt * 2 + k;
            int m = mt * 32 + ct * 2 + q;
            float denom = nA[rt * 2 + k] * nB[ct * 2 + q] + 1e-6f;
            float sim = __fdividef(acc[k][q], denom);
            float v0 = fminf(fmaxf(sim, 0.0f), 1.0f);
            float v1 = fminf(fmaxf(1.0f - sim, 0.0f), 1.0f);
            out[((t * 2 + 0) * NN + n) * NN + m] = v0;
            out[((t * 2 + 1) * NN + n) * NN + m] = v1;
        }
    }
}

// ---- layer-0 edge update + aggregation (2 i-rows per block) ----
__global__ void k_edge0(const float* __restrict__ node, const float* __restrict__ edge,
                        const float* __restrict__ ew, const float* __restrict__ eb) {
    int t = blockIdx.y, ip = blockIdx.x, f = threadIdx.x;
    int i0 = ip * 2, i1 = i0 + 1;
    float w0 = ew[0], w1 = ew[1], w2 = ew[2], b = eb[0];
    const float* xp = node + t * NN * FF + f;
    float c0 = fmaf(w0 + w1, xp[i0 * FF], b);
    float c1 = fmaf(w0 + w1, xp[i1 * FF], b);
    const float* e0p = edge + ((size_t)(t * NN + i0) * NN) * FF + f;
    const float* e1p = e0p + (size_t)NN * FF;
    float acc0 = 0.f, acc1 = 0.f;
#pragma unroll 4
    for (int j = 0; j < NN; ++j) {
        float xj = xp[j * FF];
        float a0 = fmaf(w2, e0p[j * FF], fmaf(-w1, xj, c0));
        float a1 = fmaf(w2, e1p[j * FF], fmaf(-w1, xj, c1));
        float t0 = my_tanh(a0);
        float t1 = my_tanh(a1);
        if (j != i0) acc0 += t0;
        if (j != i1) acc1 += t1;
    }
    g_aggr[(t * NN + i0) * FF + f] = acc0;
    g_aggr[(t * NN + i1) * FF + f] = acc1;
}

// ---- layer-1: recompute e0 from inputs, then layer-1 edge update + aggregation ----
__global__ void k_edge1(const float* __restrict__ node0, const float* __restrict__ node1,
                        const float* __restrict__ edge,
                        const float* __restrict__ ew, const float* __restrict__ eb) {
    int t = blockIdx.y, ip = blockIdx.x, f = threadIdx.x;
    int i0 = ip * 2, i1 = i0 + 1;
    float w00 = ew[0], w01 = ew[1], w02 = ew[2], b0 = eb[0];
    float w10 = ew[3], w11 = ew[4], w12 = ew[5], b1 = eb[1];
    const float* x0p = node0 + t * NN * FF + f;
    const float* x1p = node1 + t * NN * FF + f;
    float c0a = fmaf(w00 + w01, x0p[i0 * FF], b0);
    float c0b = fmaf(w00 + w01, x0p[i1 * FF], b0);
    float c1a = fmaf(w10 + w11, x1p[i0 * FF], b1);
    float c1b = fmaf(w10 + w11, x1p[i1 * FF], b1);
    const float* e0p = edge + ((size_t)(t * NN + i0) * NN) * FF + f;
    const float* e1p = e0p + (size_t)NN * FF;
    float acc0 = 0.f, acc1 = 0.f;
#pragma unroll 2
    for (int j = 0; j < NN; ++j) {
        float x0j = x0p[j * FF];
        float x1j = x1p[j * FF];
        float ein0 = e0p[j * FF];
        float ein1 = e1p[j * FF];
        float ea = my_tanh(fmaf(w02, ein0, fmaf(-w01, x0j, c0a)));
        float ebx = my_tanh(fmaf(w02, ein1, fmaf(-w01, x0j, c0b)));
        float ta = my_tanh(fmaf(w12, ea,  fmaf(-w11, x1j, c1a)));
        float tb = my_tanh(fmaf(w12, ebx, fmaf(-w11, x1j, c1b)));
        if (j != i0) acc0 += ta;
        if (j != i1) acc1 += tb;
    }
    g_aggr[(t * NN + i0) * FF + f] = acc0;
    g_aggr[(t * NN + i1) * FF + f] = acc1;
}

// ---- node update GEMM: y[t,n,g] = sum_f lrelu(c0*x + c1*aggr)[t,n,f] * W[g,f] ----
// grid = T*8 (16-row tiles), 256 threads, dynamic smem: WsT[128*129] + hs[16*129]
__global__ void k_gemm(const float* __restrict__ x, const float* __restrict__ cw,
                       const float* __restrict__ W, float* __restrict__ y) {
    extern __shared__ float sm[];
    float* WsT = sm;               // [f][g], pitch 129
    float* hs  = sm + 128 * 129;   // [r][f], pitch 129
    float c0 = cw[0], c1 = cw[1];
    int t = blockIdx.x >> 3;
    int r0 = (blockIdx.x & 7) * 16;
    int tid = threadIdx.x;
    for (int idx = tid; idx < FF * FF; idx += 256) {
        int g = idx >> 7, f = idx & 127;
        WsT[f * 129 + g] = W[idx];
    }
    for (int idx = tid; idx < 16 * FF; idx += 256) {
        int r = idx >> 7, f = idx & 127;
        int off = (t * NN + r0 + r) * FF + f;
        float h = fmaf(c1, g_aggr[off], c0 * x[off]);
        hs[r * 129 + f] = lrelu(h);
    }
    __syncthreads();
    int rt = tid & 7, gt = tid >> 3;   // 8 row-pairs x 32 col-quads
    float acc[2][4] = { {0.f,0.f,0.f,0.f}, {0.f,0.f,0.f,0.f} };
    for (int f = 0; f < FF; ++f) {
        float a0 = hs[(rt * 2) * 129 + f];
        float a1 = hs[(rt * 2 + 1) * 129 + f];
#pragma unroll
        for (int q = 0; q < 4; ++q) {
            float bv = WsT[f * 129 + gt * 4 + q];
            acc[0][q] = fmaf(a0, bv, acc[0][q]);
            acc[1][q] = fmaf(a1, bv, acc[1][q]);
        }
    }
#pragma unroll
    for (int k = 0; k < 2; ++k)
#pragma unroll
        for (int q = 0; q < 4; ++q)
            y[(t * NN + r0 + rt * 2 + k) * FF + gt * 4 + q] = acc[k][q];
}

// ---- BN stats: grid=F (one block per feature g), 256 threads ----
__global__ void k_bnstats(const float* __restrict__ y) {
    int g = blockIdx.x, tid = threadIdx.x;
    float s = 0.f, s2 = 0.f;
    for (int r = tid; r < TN; r += 256) {
        float v = y[r * FF + g];
        s += v;
        s2 = fmaf(v, v, s2);
    }
    __shared__ float sh1[256], sh2[256];
    sh1[tid] = s; sh2[tid] = s2;
    __syncthreads();
    for (int o = 128; o > 0; o >>= 1) {
        if (tid < o) { sh1[tid] += sh1[tid + o]; sh2[tid] += sh2[tid + o]; }
        __syncthreads();
    }
    if (tid == 0) { g_sum[g] = sh1[0]; g_sumsq[g] = sh2[0]; }
}

// ---- BN apply + LeakyReLU -> next node_feats ----
__global__ void k_bnapply(const float* __restrict__ y, const float* __restrict__ gamma,
                          const float* __restrict__ beta, float* __restrict__ xout) {
    int idx = blockIdx.x * blockDim.x + threadIdx.x;
    int f = idx & (FF - 1);
    const float inv = 1.0f / (float)TN;
    float mu = g_sum[f] * inv;
    float var = fmaf(-mu, mu, g_sumsq[f] * inv);
    float v = (y[idx] - mu) * rsqrtf(var + 1e-5f) * gamma[f] + beta[f];
    xout[idx] = lrelu(v);
}

extern "C" void kernel_launch(void* const* d_in, const int* in_sizes, int n_in,
                              void* d_out, int out_size) {
    const float* node  = (const float*)d_in[0];
    const float* edge  = (const float*)d_in[1];
    const float* ew    = (const float*)d_in[2];   // [L,3]
    const float* ebv   = (const float*)d_in[3];   // [L]
    const float* cw    = (const float*)d_in[4];   // [L,2]
    const float* nw    = (const float*)d_in[5];   // [L,F,F]
    const float* gamma = (const float*)d_in[6];   // [L,F]
    const float* beta  = (const float*)d_in[7];   // [L,F]
    float* out = (float*)d_out;

    void *p1, *p2, *py;
    cudaGetSymbolAddress(&p1, g_node1);
    cudaGetSymbolAddress(&p2, g_node2);
    cudaGetSymbolAddress(&py, g_y);
    float* node1 = (float*)p1;
    float* node2 = (float*)p2;
    float* y     = (float*)py;

    size_t gemm_smem = (size_t)(128 * 129 + 16 * 129) * sizeof(float);
    cudaFuncSetAttribute(k_gemm, cudaFuncAttributeMaxDynamicSharedMemorySize, (int)gemm_smem);

    const int OUTBLK = TT * 2 * NN * NN;

    // sim_cal on the input node features
    k_norms<<<TT, NN>>>(node);
    k_simcal<<<dim3(16, TT), 256>>>(node, out);

    // ---- layer 0 ----
    k_edge0<<<dim3(NN / 2, TT), NN>>>(node, edge, ew, ebv);
    k_gemm<<<TT * 8, 256, gemm_smem>>>(node, cw, nw, y);
    k_bnstats<<<FF, 256>>>(y);
    k_bnapply<<<(TT * NN * FF) / 512, 512>>>(y, gamma, beta, node1);
    k_norms<<<TT, NN>>>(node1);
    k_simcal<<<dim3(16, TT), 256>>>(node1, out + OUTBLK);

    // ---- layer 1 (recompute layer-0 edges on the fly; no 128MB intermediate) ----
    k_edge1<<<dim3(NN / 2, TT), NN>>>(node, node1, edge, ew, ebv);
    k_gemm<<<TT * 8, 256, gemm_smem>>>(node1, cw + 2, nw + FF * FF, y);
    k_bnstats<<<FF, 256>>>(y);
    k_bnapply<<<(TT * NN * FF) / 512, 512>>>(y, gamma + FF, beta + FF, node2);
    k_norms<<<TT, NN>>>(node2);
    k_simcal<<<dim3(16, TT), 256>>>(node2, out + 2 * OUTBLK);
}

// round 5
// speedup vs baseline: 1.0635x; 1.0635x over previous
#include <cuda_runtime.h>
#include <math.h>

#define TT 16
#define NN 128
#define FF 128
#define TN (TT*NN)

// ---- scratch (__device__ globals; no allocation allowed) ----
__device__ float g_aggr[TT*NN*FF];
__device__ float g_y[TT*NN*FF];
__device__ float g_node1[TT*NN*FF];
__device__ float g_node2[TT*NN*FF];
__device__ float g_stats[4*FF];      // [sum0, sumsq0, sum1, sumsq1]
__device__ float g_nrm[TT*NN];

__device__ __forceinline__ float tanh_fast(float x) {
    float y; asm("tanh.approx.f32 %0, %1;" : "=f"(y) : "f"(x)); return y;
}
__device__ __forceinline__ float lrelu(float v) { return v >= 0.0f ? v : 0.01f * v; }

// ---- pre: input row norms (warp per row, float4) + zero BN stat accumulators ----
// grid 256, block 256
__global__ void k_pre(const float* __restrict__ x) {
    int tid = threadIdx.x;
    if (blockIdx.x < 2) g_stats[blockIdx.x * 256 + tid] = 0.0f;
    int warp = tid >> 5, lane = tid & 31;
    int row = blockIdx.x * 8 + warp;
    float4 v = ((const float4*)(x + row * FF))[lane];
    float s = v.x * v.x + v.y * v.y + v.z * v.z + v.w * v.w;
#pragma unroll
    for (int o = 16; o; o >>= 1) s += __shfl_down_sync(0xffffffffu, s, o);
    if (lane == 0) g_nrm[row] = sqrtf(s);
}

// ---- sim_cal: grid=(16 tiles, T), 256 threads, 2x2 register tile per thread ----
__global__ void k_simcal(const float* __restrict__ x, float* __restrict__ out) {
    __shared__ float As[32][33], Bs[32][33];
    __shared__ float nA[32], nB[32];
    int t = blockIdx.y;
    int nt = blockIdx.x >> 2, mt = blockIdx.x & 3;
    int tid = threadIdx.x;
    if (tid < 32)       nA[tid]      = g_nrm[t * NN + nt * 32 + tid];
    else if (tid < 64)  nB[tid - 32] = g_nrm[t * NN + mt * 32 + (tid - 32)];
    int rt = tid & 15, ct = tid >> 4;
    float a00 = 0.f, a01 = 0.f, a10 = 0.f, a11 = 0.f;
    for (int fc = 0; fc < FF; fc += 32) {
        __syncthreads();
        int rr = tid >> 5, cc = tid & 31;
#pragma unroll
        for (int k = 0; k < 4; ++k) {
            As[rr + k * 8][cc] = x[(t * NN + nt * 32 + rr + k * 8) * FF + fc + cc];
            Bs[rr + k * 8][cc] = x[(t * NN + mt * 32 + rr + k * 8) * FF + fc + cc];
        }
        __syncthreads();
#pragma unroll
        for (int ff = 0; ff < 32; ++ff) {
            float r0 = As[rt * 2][ff], r1 = As[rt * 2 + 1][ff];
            float c0 = Bs[ct * 2][ff], c1 = Bs[ct * 2 + 1][ff];
            a00 = fmaf(r0, c0, a00); a01 = fmaf(r0, c1, a01);
            a10 = fmaf(r1, c0, a10); a11 = fmaf(r1, c1, a11);
        }
    }
    float acc[2][2] = { {a00, a01}, {a10, a11} };
#pragma unroll
    for (int k = 0; k < 2; ++k) {
#pragma unroll
        for (int q = 0; q < 2; ++q) {
            int n = nt * 32 + rt * 2 + k;
            int m = mt * 32 + ct * 2 + q;
            float denom = nA[rt * 2 + k] * nB[ct * 2 + q] + 1e-6f;
            float sim = __fdividef(acc[k][q], denom);
            float v0 = fminf(fmaxf(sim, 0.0f), 1.0f);
            float v1 = fminf(fmaxf(1.0f - sim, 0.0f), 1.0f);
            out[((t * 2 + 0) * NN + n) * NN + m] = v0;
            out[((t * 2 + 1) * NN + n) * NN + m] = v1;
        }
    }
}

// ---- layer-0 edge update + aggregation: grid (32, T), block 128 (4 i-rows, float4/lane) ----
__global__ void __launch_bounds__(128) k_edge0(
        const float* __restrict__ node, const float* __restrict__ edge,
        const float* __restrict__ ew, const float* __restrict__ eb) {
    int t = blockIdx.y;
    int lane = threadIdx.x & 31, w = threadIdx.x >> 5;
    int i = blockIdx.x * 4 + w;
    float w0 = ew[0], w1 = ew[1], w2 = ew[2], b = eb[0];
    const float4* x4 = (const float4*)(node + t * NN * FF);
    float4 xi = x4[i * 32 + lane];
    float cx = fmaf(w0 + w1, xi.x, b), cy = fmaf(w0 + w1, xi.y, b);
    float cz = fmaf(w0 + w1, xi.z, b), cw_ = fmaf(w0 + w1, xi.w, b);
    const float4* e4 = (const float4*)(edge + ((size_t)(t * NN + i) * NN) * FF);
    float ax = 0.f, ay = 0.f, az = 0.f, aw = 0.f;
#pragma unroll 8
    for (int j = 0; j < NN; ++j) {
        float4 e = e4[j * 32 + lane];
        float4 xj = x4[j * 32 + lane];
        float rx = tanh_fast(fmaf(w2, e.x, fmaf(-w1, xj.x, cx)));
        float ry = tanh_fast(fmaf(w2, e.y, fmaf(-w1, xj.y, cy)));
        float rz = tanh_fast(fmaf(w2, e.z, fmaf(-w1, xj.z, cz)));
        float rw = tanh_fast(fmaf(w2, e.w, fmaf(-w1, xj.w, cw_)));
        if (j != i) { ax += rx; ay += ry; az += rz; aw += rw; }
    }
    float4 acc; acc.x = ax; acc.y = ay; acc.z = az; acc.w = aw;
    ((float4*)(g_aggr + (t * NN + i) * FF))[lane] = acc;
}

// ---- layer-1: recompute e0, chain layer-1 tanh, aggregate ----
__global__ void __launch_bounds__(128) k_edge1(
        const float* __restrict__ node0, const float* __restrict__ node1,
        const float* __restrict__ edge,
        const float* __restrict__ ew, const float* __restrict__ eb) {
    int t = blockIdx.y;
    int lane = threadIdx.x & 31, w = threadIdx.x >> 5;
    int i = blockIdx.x * 4 + w;
    float w00 = ew[0], w01 = ew[1], w02 = ew[2], b0 = eb[0];
    float w10 = ew[3], w11 = ew[4], w12 = ew[5], b1 = eb[1];
    const float4* x04 = (const float4*)(node0 + t * NN * FF);
    const float4* x14 = (const float4*)(node1 + t * NN * FF);
    float4 xi0 = x04[i * 32 + lane];
    float4 xi1 = x14[i * 32 + lane];
    float c0x = fmaf(w00 + w01, xi0.x, b0), c0y = fmaf(w00 + w01, xi0.y, b0);
    float c0z = fmaf(w00 + w01, xi0.z, b0), c0w = fmaf(w00 + w01, xi0.w, b0);
    float c1x = fmaf(w10 + w11, xi1.x, b1), c1y = fmaf(w10 + w11, xi1.y, b1);
    float c1z = fmaf(w10 + w11, xi1.z, b1), c1w = fmaf(w10 + w11, xi1.w, b1);
    const float4* e4 = (const float4*)(edge + ((size_t)(t * NN + i) * NN) * FF);
    float ax = 0.f, ay = 0.f, az = 0.f, aw = 0.f;
#pragma unroll 8
    for (int j = 0; j < NN; ++j) {
        float4 e  = e4[j * 32 + lane];
        float4 x0 = x04[j * 32 + lane];
        float4 x1 = x14[j * 32 + lane];
        float e0x = tanh_fast(fmaf(w02, e.x, fmaf(-w01, x0.x, c0x)));
        float e0y = tanh_fast(fmaf(w02, e.y, fmaf(-w01, x0.y, c0y)));
        float e0z = tanh_fast(fmaf(w02, e.z, fmaf(-w01, x0.z, c0z)));
        float e0w = tanh_fast(fmaf(w02, e.w, fmaf(-w01, x0.w, c0w)));
        float rx = tanh_fast(fmaf(w12, e0x, fmaf(-w11, x1.x, c1x)));
        float ry = tanh_fast(fmaf(w12, e0y, fmaf(-w11, x1.y, c1y)));
        float rz = tanh_fast(fmaf(w12, e0z, fmaf(-w11, x1.z, c1z)));
        float rw = tanh_fast(fmaf(w12, e0w, fmaf(-w11, x1.w, c1w)));
        if (j != i) { ax += rx; ay += ry; az += rz; aw += rw; }
    }
    float4 acc; acc.x = ax; acc.y = ay; acc.z = az; acc.w = aw;
    ((float4*)(g_aggr + (t * NN + i) * FF))[lane] = acc;
}

// ---- node GEMM + fused BN-stat accumulation ----
// grid T*8 (16-row tiles), 256 threads; dyn smem: Ws[128][132] + hs[16][129]
__global__ void __launch_bounds__(256) k_gemm(
        const float* __restrict__ x, const float* __restrict__ cw,
        const float* __restrict__ W, float* __restrict__ y, float* __restrict__ stats) {
    extern __shared__ float sm[];
    float* Ws = sm;                 // [g][f], pitch 132 (float4-aligned, 2-way conflict max)
    float* hs = sm + 128 * 132;     // [r][f], pitch 129
    float c0 = cw[0], c1 = cw[1];
    int t = blockIdx.x >> 3;
    int r0 = (blockIdx.x & 7) * 16;
    int tid = threadIdx.x;
    // stage W coalesced with float4 loads+stores
    const float4* W4 = (const float4*)W;
#pragma unroll
    for (int k = 0; k < 16; ++k) {
        int idx = tid + k * 256;        // float4 index
        int g = idx >> 5, f4 = idx & 31;
        ((float4*)(Ws + g * 132))[f4] = W4[idx];
    }
    // stage h = lrelu(c0*x + c1*aggr)
    for (int idx = tid; idx < 16 * FF; idx += 256) {
        int r = idx >> 7, f = idx & 127;
        int off = (t * NN + r0 + r) * FF + f;
        float h = fmaf(c1, g_aggr[off], c0 * x[off]);
        hs[r * 129 + f] = lrelu(h);
    }
    __syncthreads();
    int rt = tid & 7, gt = tid >> 3;   // 8 row-pairs x 32 col-quads
    float acc[2][4] = { {0.f,0.f,0.f,0.f}, {0.f,0.f,0.f,0.f} };
#pragma unroll 4
    for (int f = 0; f < FF; ++f) {
        float a0 = hs[(rt * 2) * 129 + f];
        float a1 = hs[(rt * 2 + 1) * 129 + f];
#pragma unroll
        for (int q = 0; q < 4; ++q) {
            float bv = Ws[(gt * 4 + q) * 132 + f];
            acc[0][q] = fmaf(a0, bv, acc[0][q]);
            acc[1][q] = fmaf(a1, bv, acc[1][q]);
        }
    }
    // vector stores
#pragma unroll
    for (int k = 0; k < 2; ++k) {
        float4 v; v.x = acc[k][0]; v.y = acc[k][1]; v.z = acc[k][2]; v.w = acc[k][3];
        *(float4*)(y + (t * NN + r0 + rt * 2 + k) * FF + gt * 4) = v;
    }
    // fused BN stats: reduce block's 16 rows per column via width-8 shfl, then atomics
#pragma unroll
    for (int q = 0; q < 4; ++q) {
        float s  = acc[0][q] + acc[1][q];
        float ss = fmaf(acc[0][q], acc[0][q], acc[1][q] * acc[1][q]);
#pragma unroll
        for (int o = 4; o; o >>= 1) {
            s  += __shfl_down_sync(0xffffffffu, s,  o, 8);
            ss += __shfl_down_sync(0xffffffffu, ss, o, 8);
        }
        if (rt == 0) {
            int g = gt * 4 + q;
            atomicAdd(&stats[g], s);
            atomicAdd(&stats[FF + g], ss);
        }
    }
}

// ---- fused BN-apply + LeakyReLU + row norms: grid 256, block 256 (warp per row) ----
__global__ void k_bnfuse(const float* __restrict__ y, const float* __restrict__ gamma,
                         const float* __restrict__ beta, float* __restrict__ xout,
                         const float* __restrict__ stats) {
    int warp = threadIdx.x >> 5, lane = threadIdx.x & 31;
    int row = blockIdx.x * 8 + warp;
    const float inv = 1.0f / (float)TN;
    float4 smv = ((const float4*)stats)[lane];
    float4 sqv = ((const float4*)(stats + FF))[lane];
    float4 gv  = ((const float4*)gamma)[lane];
    float4 bv  = ((const float4*)beta)[lane];
    float4 yv  = ((const float4*)(y + row * FF))[lane];
    float4 o;
    {
        float mu = smv.x * inv; float var = fmaf(-mu, mu, sqv.x * inv);
        o.x = lrelu(fmaf((yv.x - mu) * rsqrtf(var + 1e-5f), gv.x, bv.x));
        mu = smv.y * inv; var = fmaf(-mu, mu, sqv.y * inv);
        o.y = lrelu(fmaf((yv.y - mu) * rsqrtf(var + 1e-5f), gv.y, bv.y));
        mu = smv.z * inv; var = fmaf(-mu, mu, sqv.z * inv);
        o.z = lrelu(fmaf((yv.z - mu) * rsqrtf(var + 1e-5f), gv.z, bv.z));
        mu = smv.w * inv; var = fmaf(-mu, mu, sqv.w * inv);
        o.w = lrelu(fmaf((yv.w - mu) * rsqrtf(var + 1e-5f), gv.w, bv.w));
    }
    ((float4*)(xout + row * FF))[lane] = o;
    float s = o.x * o.x + o.y * o.y + o.z * o.z + o.w * o.w;
#pragma unroll
    for (int off = 16; off; off >>= 1) s += __shfl_down_sync(0xffffffffu, s, off);
    if (lane == 0) g_nrm[row] = sqrtf(s);
}

extern "C" void kernel_launch(void* const* d_in, const int* in_sizes, int n_in,
                              void* d_out, int out_size) {
    const float* node  = (const float*)d_in[0];
    const float* edge  = (const float*)d_in[1];
    const float* ew    = (const float*)d_in[2];   // [L,3]
    const float* ebv   = (const float*)d_in[3];   // [L]
    const float* cw    = (const float*)d_in[4];   // [L,2]
    const float* nw    = (const float*)d_in[5];   // [L,F,F]
    const float* gamma = (const float*)d_in[6];   // [L,F]
    const float* beta  = (const float*)d_in[7];   // [L,F]
    float* out = (float*)d_out;

    void *p1, *p2, *py, *ps;
    cudaGetSymbolAddress(&p1, g_node1);
    cudaGetSymbolAddress(&p2, g_node2);
    cudaGetSymbolAddress(&py, g_y);
    cudaGetSymbolAddress(&ps, g_stats);
    float* node1 = (float*)p1;
    float* node2 = (float*)p2;
    float* y     = (float*)py;
    float* st    = (float*)ps;

    size_t gemm_smem = (size_t)(128 * 132 + 16 * 129) * sizeof(float);
    cudaFuncSetAttribute(k_gemm, cudaFuncAttributeMaxDynamicSharedMemorySize, (int)gemm_smem);

    const int OUTBLK = TT * 2 * NN * NN;

    k_pre<<<256, 256>>>(node);                           // norms(input) + zero stats
    k_simcal<<<dim3(16, TT), 256>>>(node, out);

    // ---- layer 0 ----
    k_edge0<<<dim3(32, TT), 128>>>(node, edge, ew, ebv);
    k_gemm<<<TT * 8, 256, gemm_smem>>>(node, cw, nw, y, st);
    k_bnfuse<<<256, 256>>>(y, gamma, beta, node1, st);
    k_simcal<<<dim3(16, TT), 256>>>(node1, out + OUTBLK);

    // ---- layer 1 (recompute layer-0 edges on the fly) ----
    k_edge1<<<dim3(32, TT), 128>>>(node, node1, edge, ew, ebv);
    k_gemm<<<TT * 8, 256, gemm_smem>>>(node1, cw + 2, nw + FF * FF, y, st + 2 * FF);
    k_bnfuse<<<256, 256>>>(y, gamma + FF, beta + FF, node2, st + 2 * FF);
    k_simcal<<<dim3(16, TT), 256>>>(node2, out + 2 * OUTBLK);
}

// round 7
// speedup vs baseline: 1.3371x; 1.2572x over previous
#include <cuda_runtime.h>
#include <math.h>

#define TT 16
#define NN 128
#define FF 128
#define TN (TT*NN)

// ---- scratch (__device__ globals; no allocation allowed) ----
__device__ float g_aggr[TT*NN*FF];
__device__ float g_y[TT*NN*FF];
__device__ float g_node1[TT*NN*FF];
__device__ float g_node2[TT*NN*FF];
__device__ float g_stats[4*FF];      // [sum0(128), sumsq0(128), sum1, sumsq1]

__device__ const int c_nt[10] = {0,0,0,0,1,1,1,2,2,3};
__device__ const int c_mt[10] = {0,1,2,3,1,2,3,2,3,3};

__device__ __forceinline__ float tanh_fast(float x) {
    float y; asm("tanh.approx.f32 %0, %1;" : "=f"(y) : "f"(x)); return y;
}
__device__ __forceinline__ float lrelu(float v) { return v >= 0.0f ? v : 0.01f * v; }
__device__ __forceinline__ float dot4(float4 a, float4 b, float acc) {
    return fmaf(a.x, b.x, fmaf(a.y, b.y, fmaf(a.z, b.z, fmaf(a.w, b.w, acc))));
}

// ---- sim_cal: grid=(10 sym tiles, T), 256 threads; norms computed in-kernel ----
__global__ void __launch_bounds__(256) k_simcal(const float* __restrict__ x,
                                                float* __restrict__ out) {
    __shared__ float4 As[32*33], Bs[32*33];
    __shared__ float nA[32], nB[32];
    int t = blockIdx.y;
    int nt = c_nt[blockIdx.x], mt = c_mt[blockIdx.x];
    int tid = threadIdx.x;
    const float4* xa = (const float4*)(x + (t * NN + nt * 32) * FF);
    const float4* xb = (const float4*)(x + (t * NN + mt * 32) * FF);
#pragma unroll
    for (int i = 0; i < 4; ++i) {
        int idx = tid + i * 256;
        int r = idx >> 5, k = idx & 31;
        As[r * 33 + k] = xa[idx];
        Bs[r * 33 + k] = xb[idx];
    }
    __syncthreads();
    // norms from staged tiles (warps 0-1)
    if (tid < 64) {
        int r = tid & 31;
        const float4* src = (tid < 32) ? As : Bs;
        float s = 0.f;
#pragma unroll 8
        for (int k = 0; k < 32; ++k) { float4 v = src[r * 33 + k]; s = dot4(v, v, s); }
        if (tid < 32) nA[r] = sqrtf(s); else nB[r] = sqrtf(s);
    }
    int ra = tid & 15, cb = tid >> 4;     // rows {ra, ra+16}, cols {cb, cb+16}
    float a00 = 0.f, a01 = 0.f, a10 = 0.f, a11 = 0.f;
#pragma unroll 8
    for (int k = 0; k < 32; ++k) {
        float4 r0 = As[ra * 33 + k], r1 = As[(ra + 16) * 33 + k];
        float4 q0 = Bs[cb * 33 + k], q1 = Bs[(cb + 16) * 33 + k];
        a00 = dot4(r0, q0, a00); a01 = dot4(r0, q1, a01);
        a10 = dot4(r1, q0, a10); a11 = dot4(r1, q1, a11);
    }
    __syncthreads();   // nA/nB visible
    float na[2] = { nA[ra], nA[ra + 16] };
    float nb[2] = { nB[cb], nB[cb + 16] };
    float acc[2][2] = { {a00, a01}, {a10, a11} };
    bool mir = (nt != mt);
    long ob0 = (long)(t * 2 + 0) * NN * NN;
    long ob1 = (long)(t * 2 + 1) * NN * NN;
#pragma unroll
    for (int k = 0; k < 2; ++k) {
#pragma unroll
        for (int q = 0; q < 2; ++q) {
            int n = nt * 32 + ra + k * 16;
            int m = mt * 32 + cb + q * 16;
            float sim = __fdividef(acc[k][q], na[k] * nb[q] + 1e-6f);
            float v0 = fminf(fmaxf(sim, 0.0f), 1.0f);
            float v1 = fminf(fmaxf(1.0f - sim, 0.0f), 1.0f);
            out[ob0 + n * NN + m] = v0;
            out[ob1 + n * NN + m] = v1;
            if (mir) {
                out[ob0 + m * NN + n] = v0;
                out[ob1 + m * NN + n] = v1;
            }
        }
    }
}

// ---- layer-0 edge update + aggregation: grid (32, T), block 128 (4 i-rows, float4/lane) ----
__global__ void __launch_bounds__(128) k_edge0(
        const float* __restrict__ node, const float* __restrict__ edge,
        const float* __restrict__ ew, const float* __restrict__ eb,
        float* __restrict__ stats) {
    if (blockIdx.x == 0 && blockIdx.y == 0) {
        stats[threadIdx.x] = 0.0f; stats[threadIdx.x + 128] = 0.0f;
    }
    int t = blockIdx.y;
    int lane = threadIdx.x & 31, w = threadIdx.x >> 5;
    int i = blockIdx.x * 4 + w;
    float w0 = ew[0], w1 = ew[1], w2 = ew[2], b = eb[0];
    const float4* x4 = (const float4*)(node + t * NN * FF);
    float4 xi = x4[i * 32 + lane];
    float cx = fmaf(w0 + w1, xi.x, b), cy = fmaf(w0 + w1, xi.y, b);
    float cz = fmaf(w0 + w1, xi.z, b), cw_ = fmaf(w0 + w1, xi.w, b);
    const float4* e4 = (const float4*)(edge + ((size_t)(t * NN + i) * NN) * FF);
    float ax = 0.f, ay = 0.f, az = 0.f, aw = 0.f;
#pragma unroll 8
    for (int j = 0; j < NN; ++j) {
        float4 e = e4[j * 32 + lane];
        float4 xj = x4[j * 32 + lane];
        ax += tanh_fast(fmaf(w2, e.x, fmaf(-w1, xj.x, cx)));
        ay += tanh_fast(fmaf(w2, e.y, fmaf(-w1, xj.y, cy)));
        az += tanh_fast(fmaf(w2, e.z, fmaf(-w1, xj.z, cz)));
        aw += tanh_fast(fmaf(w2, e.w, fmaf(-w1, xj.w, cw_)));
    }
    // subtract diagonal (j == i)
    float4 eii = e4[i * 32 + lane];
    ax -= tanh_fast(fmaf(w2, eii.x, fmaf(-w1, xi.x, cx)));
    ay -= tanh_fast(fmaf(w2, eii.y, fmaf(-w1, xi.y, cy)));
    az -= tanh_fast(fmaf(w2, eii.z, fmaf(-w1, xi.z, cz)));
    aw -= tanh_fast(fmaf(w2, eii.w, fmaf(-w1, xi.w, cw_)));
    float4 acc; acc.x = ax; acc.y = ay; acc.z = az; acc.w = aw;
    ((float4*)(g_aggr + (t * NN + i) * FF))[lane] = acc;
}

// ---- layer-1: recompute e0 on the fly, chain layer-1 tanh, aggregate ----
__global__ void __launch_bounds__(128) k_edge1(
        const float* __restrict__ node0, const float* __restrict__ node1,
        const float* __restrict__ edge,
        const float* __restrict__ ew, const float* __restrict__ eb,
        float* __restrict__ stats) {
    if (blockIdx.x == 0 && blockIdx.y == 0) {
        stats[threadIdx.x] = 0.0f; stats[threadIdx.x + 128] = 0.0f;
    }
    int t = blockIdx.y;
    int lane = threadIdx.x & 31, w = threadIdx.x >> 5;
    int i = blockIdx.x * 4 + w;
    float w00 = ew[0], w01 = ew[1], w02 = ew[2], b0 = eb[0];
    float w10 = ew[3], w11 = ew[4], w12 = ew[5], b1 = eb[1];
    const float4* x04 = (const float4*)(node0 + t * NN * FF);
    const float4* x14 = (const float4*)(node1 + t * NN * FF);
    float4 xi0 = x04[i * 32 + lane];
    float4 xi1 = x14[i * 32 + lane];
    float c0x = fmaf(w00 + w01, xi0.x, b0), c0y = fmaf(w00 + w01, xi0.y, b0);
    float c0z = fmaf(w00 + w01, xi0.z, b0), c0w = fmaf(w00 + w01, xi0.w, b0);
    float c1x = fmaf(w10 + w11, xi1.x, b1), c1y = fmaf(w10 + w11, xi1.y, b1);
    float c1z = fmaf(w10 + w11, xi1.z, b1), c1w = fmaf(w10 + w11, xi1.w, b1);
    const float4* e4 = (const float4*)(edge + ((size_t)(t * NN + i) * NN) * FF);
    float ax = 0.f, ay = 0.f, az = 0.f, aw = 0.f;
#pragma unroll 8
    for (int j = 0; j < NN; ++j) {
        float4 e  = e4[j * 32 + lane];
        float4 x0 = x04[j * 32 + lane];
        float4 x1 = x14[j * 32 + lane];
        float e0x = tanh_fast(fmaf(w02, e.x, fmaf(-w01, x0.x, c0x)));
        float e0y = tanh_fast(fmaf(w02, e.y, fmaf(-w01, x0.y, c0y)));
        float e0z = tanh_fast(fmaf(w02, e.z, fmaf(-w01, x0.z, c0z)));
        float e0w = tanh_fast(fmaf(w02, e.w, fmaf(-w01, x0.w, c0w)));
        ax += tanh_fast(fmaf(w12, e0x, fmaf(-w11, x1.x, c1x)));
        ay += tanh_fast(fmaf(w12, e0y, fmaf(-w11, x1.y, c1y)));
        az += tanh_fast(fmaf(w12, e0z, fmaf(-w11, x1.z, c1z)));
        aw += tanh_fast(fmaf(w12, e0w, fmaf(-w11, x1.w, c1w)));
    }
    // subtract diagonal (j == i)
    {
        float4 e = e4[i * 32 + lane];
        float e0x = tanh_fast(fmaf(w02, e.x, fmaf(-w01, xi0.x, c0x)));
        float e0y = tanh_fast(fmaf(w02, e.y, fmaf(-w01, xi0.y, c0y)));
        float e0z = tanh_fast(fmaf(w02, e.z, fmaf(-w01, xi0.z, c0z)));
        float e0w = tanh_fast(fmaf(w02, e.w, fmaf(-w01, xi0.w, c0w)));
        ax -= tanh_fast(fmaf(w12, e0x, fmaf(-w11, xi1.x, c1x)));
        ay -= tanh_fast(fmaf(w12, e0y, fmaf(-w11, xi1.y, c1y)));
        az -= tanh_fast(fmaf(w12, e0z, fmaf(-w11, xi1.z, c1z)));
        aw -= tanh_fast(fmaf(w12, e0w, fmaf(-w11, xi1.w, c1w)));
    }
    float4 acc; acc.x = ax; acc.y = ay; acc.z = az; acc.w = aw;
    ((float4*)(g_aggr + (t * NN + i) * FF))[lane] = acc;
}

// ---- node GEMM (all-float4 mainloop) + fused BN-stat accumulation ----
// grid T*8 (16-row tiles), 256 threads; dyn smem: Ws4[128][33] + hs4[16][33]
__global__ void __launch_bounds__(256) k_gemm(
        const float* __restrict__ x, const float* __restrict__ cw,
        const float* __restrict__ W, float* __restrict__ y, float* __restrict__ stats) {
    extern __shared__ float4 sm4[];
    float4* Ws = sm4;               // [g][k], pitch 33 float4
    float4* hs = sm4 + 128 * 33;    // [r][k], pitch 33 float4
    float c0 = cw[0], c1 = cw[1];
    int t = blockIdx.x >> 3;
    int r0 = (blockIdx.x & 7) * 16;
    int tid = threadIdx.x;
    const float4* W4 = (const float4*)W;
#pragma unroll
    for (int i = 0; i < 16; ++i) {
        int idx = tid + i * 256;
        int g = idx >> 5, k = idx & 31;
        Ws[g * 33 + k] = W4[idx];
    }
    const float4* x4 = (const float4*)(x + (t * NN + r0) * FF);
    const float4* a4 = (const float4*)(g_aggr + (t * NN + r0) * FF);
#pragma unroll
    for (int i = 0; i < 2; ++i) {
        int idx = tid + i * 256;
        int r = idx >> 5, k = idx & 31;
        float4 xv = x4[idx], av = a4[idx], h;
        h.x = lrelu(fmaf(c1, av.x, c0 * xv.x));
        h.y = lrelu(fmaf(c1, av.y, c0 * xv.y));
        h.z = lrelu(fmaf(c1, av.z, c0 * xv.z));
        h.w = lrelu(fmaf(c1, av.w, c0 * xv.w));
        hs[r * 33 + k] = h;
    }
    __syncthreads();
    int rt = tid & 7, gt = tid >> 3;   // rows {rt, rt+8}, g's gt*4..+3
    float acc[2][4] = { {0.f,0.f,0.f,0.f}, {0.f,0.f,0.f,0.f} };
#pragma unroll 4
    for (int k = 0; k < 32; ++k) {
        float4 a0 = hs[rt * 33 + k];
        float4 a1 = hs[(rt + 8) * 33 + k];
#pragma unroll
        for (int q = 0; q < 4; ++q) {
            float4 wv = Ws[(gt * 4 + q) * 33 + k];
            acc[0][q] = dot4(a0, wv, acc[0][q]);
            acc[1][q] = dot4(a1, wv, acc[1][q]);
        }
    }
    float4 v0; v0.x = acc[0][0]; v0.y = acc[0][1]; v0.z = acc[0][2]; v0.w = acc[0][3];
    float4 v1; v1.x = acc[1][0]; v1.y = acc[1][1]; v1.z = acc[1][2]; v1.w = acc[1][3];
    *(float4*)(y + (t * NN + r0 + rt) * FF + gt * 4) = v0;
    *(float4*)(y + (t * NN + r0 + rt + 8) * FF + gt * 4) = v1;
    // fused BN stats: width-8 shfl reduce over the block's 16 rows, then atomics
#pragma unroll
    for (int q = 0; q < 4; ++q) {
        float s  = acc[0][q] + acc[1][q];
        float ss = fmaf(acc[0][q], acc[0][q], acc[1][q] * acc[1][q]);
#pragma unroll
        for (int o = 4; o; o >>= 1) {
            s  += __shfl_down_sync(0xffffffffu, s,  o, 8);
            ss += __shfl_down_sync(0xffffffffu, ss, o, 8);
        }
        if (rt == 0) {
            int g = gt * 4 + q;
            atomicAdd(&stats[g], s);
            atomicAdd(&stats[FF + g], ss);
        }
    }
}

// ---- BN-apply + LeakyReLU: grid 256, block 256, one float4 per thread ----
__global__ void k_bnfuse(const float* __restrict__ y, const float* __restrict__ gamma,
                         const float* __restrict__ beta, float* __restrict__ xout,
                         const float* __restrict__ stats) {
    int idx = blockIdx.x * blockDim.x + threadIdx.x;   // float4 index
    int f4 = idx & 31;
    const float inv = 1.0f / (float)TN;
    float4 smv = ((const float4*)stats)[f4];
    float4 sqv = ((const float4*)(stats + FF))[f4];
    float4 gv  = ((const float4*)gamma)[f4];
    float4 bv  = ((const float4*)beta)[f4];
    float4 yv  = ((const float4*)y)[idx];
    float4 o;
    float mu = smv.x * inv; float var = fmaf(-mu, mu, sqv.x * inv);
    o.x = lrelu(fmaf((yv.x - mu) * rsqrtf(var + 1e-5f), gv.x, bv.x));
    mu = smv.y * inv; var = fmaf(-mu, mu, sqv.y * inv);
    o.y = lrelu(fmaf((yv.y - mu) * rsqrtf(var + 1e-5f), gv.y, bv.y));
    mu = smv.z * inv; var = fmaf(-mu, mu, sqv.z * inv);
    o.z = lrelu(fmaf((yv.z - mu) * rsqrtf(var + 1e-5f), gv.z, bv.z));
    mu = smv.w * inv; var = fmaf(-mu, mu, sqv.w * inv);
    o.w = lrelu(fmaf((yv.w - mu) * rsqrtf(var + 1e-5f), gv.w, bv.w));
    ((float4*)xout)[idx] = o;
}

extern "C" void kernel_launch(void* const* d_in, const int* in_sizes, int n_in,
                              void* d_out, int out_size) {
    const float* node  = (const float*)d_in[0];
    const float* edge  = (const float*)d_in[1];
    const float* ew    = (const float*)d_in[2];   // [L,3]
    const float* ebv   = (const float*)d_in[3];   // [L]
    const float* cw    = (const float*)d_in[4];   // [L,2]
    const float* nw    = (const float*)d_in[5];   // [L,F,F]
    const float* gamma = (const float*)d_in[6];   // [L,F]
    const float* beta  = (const float*)d_in[7];   // [L,F]
    float* out = (float*)d_out;

    void *p1, *p2, *py, *ps;
    cudaGetSymbolAddress(&p1, g_node1);
    cudaGetSymbolAddress(&p2, g_node2);
    cudaGetSymbolAddress(&py, g_y);
    cudaGetSymbolAddress(&ps, g_stats);
    float* node1 = (float*)p1;
    float* node2 = (float*)p2;
    float* y     = (float*)py;
    float* st    = (float*)ps;

    size_t gemm_smem = (size_t)(128 * 33 + 16 * 33) * sizeof(float4);
    cudaFuncSetAttribute(k_gemm, cudaFuncAttributeMaxDynamicSharedMemorySize, (int)gemm_smem);

    const int OUTBLK = TT * 2 * NN * NN;

    k_simcal<<<dim3(10, TT), 256>>>(node, out);

    // ---- layer 0 ----
    k_edge0<<<dim3(32, TT), 128>>>(node, edge, ew, ebv, st);
    k_gemm<<<TT * 8, 256, gemm_smem>>>(node, cw, nw, y, st);
    k_bnfuse<<<256, 256>>>(y, gamma, beta, node1, st);
    k_simcal<<<dim3(10, TT), 256>>>(node1, out + OUTBLK);

    // ---- layer 1 (recompute layer-0 edges on the fly) ----
    k_edge1<<<dim3(32, TT), 128>>>(node, node1, edge, ew, ebv, st + 2 * FF);
    k_gemm<<<TT * 8, 256, gemm_smem>>>(node1, cw + 2, nw + FF * FF, y, st + 2 * FF);
    k_bnfuse<<<256, 256>>>(y, gamma + FF, beta + FF, node2, st + 2 * FF);
    k_simcal<<<dim3(10, TT), 256>>>(node2, out + 2 * OUTBLK);
}

// round 10
// speedup vs baseline: 1.8824x; 1.4078x over previous
#include <cuda_runtime.h>
#include <math.h>

#define TT 16
#define NN 128
#define FF 128
#define TN (TT*NN)

// ---- scratch (__device__ globals; no allocation allowed) ----
__device__ float g_aggrA[TT*NN*FF];   // j in [0,64)
__device__ float g_aggrB[TT*NN*FF];   // j in [64,128)
__device__ float g_y[TT*NN*FF];
__device__ float g_node1[TT*NN*FF];
__device__ float g_node2[TT*NN*FF];
__device__ float g_stats[4*FF];       // [sum0(128), sumsq0(128), sum1, sumsq1]

__device__ const int c_nt[10] = {0,0,0,0,1,1,1,2,2,3};
__device__ const int c_mt[10] = {0,1,2,3,1,2,3,2,3,3};

__device__ __forceinline__ float tanh_fast(float x) {
    float y; asm("tanh.approx.f32 %0, %1;" : "=f"(y) : "f"(x)); return y;
}
__device__ __forceinline__ float lrelu(float v) { return v >= 0.0f ? v : 0.01f * v; }
__device__ __forceinline__ float dot4(float4 a, float4 b, float acc) {
    return fmaf(a.x, b.x, fmaf(a.y, b.y, fmaf(a.z, b.z, fmaf(a.w, b.w, acc))));
}

// ---- sim_cal: grid=(10 sym tiles, T), 256 threads; norms computed in-kernel ----
__global__ void __launch_bounds__(256) k_simcal(const float* __restrict__ x,
                                                float* __restrict__ out) {
    __shared__ float4 As[32*33], Bs[32*33];
    __shared__ float nA[32], nB[32];
    int t = blockIdx.y;
    int nt = c_nt[blockIdx.x], mt = c_mt[blockIdx.x];
    int tid = threadIdx.x;
    const float4* xa = (const float4*)(x + (t * NN + nt * 32) * FF);
    const float4* xb = (const float4*)(x + (t * NN + mt * 32) * FF);
#pragma unroll
    for (int i = 0; i < 4; ++i) {
        int idx = tid + i * 256;
        int r = idx >> 5, k = idx & 31;
        As[r * 33 + k] = xa[idx];
        Bs[r * 33 + k] = xb[idx];
    }
    __syncthreads();
    if (tid < 64) {
        int r = tid & 31;
        const float4* src = (tid < 32) ? As : Bs;
        float s = 0.f;
#pragma unroll 8
        for (int k = 0; k < 32; ++k) { float4 v = src[r * 33 + k]; s = dot4(v, v, s); }
        if (tid < 32) nA[r] = sqrtf(s); else nB[r] = sqrtf(s);
    }
    int ra = tid & 15, cb = tid >> 4;     // rows {ra, ra+16}, cols {cb, cb+16}
    float a00 = 0.f, a01 = 0.f, a10 = 0.f, a11 = 0.f;
#pragma unroll 8
    for (int k = 0; k < 32; ++k) {
        float4 r0 = As[ra * 33 + k], r1 = As[(ra + 16) * 33 + k];
        float4 q0 = Bs[cb * 33 + k], q1 = Bs[(cb + 16) * 33 + k];
        a00 = dot4(r0, q0, a00); a01 = dot4(r0, q1, a01);
        a10 = dot4(r1, q0, a10); a11 = dot4(r1, q1, a11);
    }
    __syncthreads();
    float na[2] = { nA[ra], nA[ra + 16] };
    float nb[2] = { nB[cb], nB[cb + 16] };
    float acc[2][2] = { {a00, a01}, {a10, a11} };
    bool mir = (nt != mt);
    long ob0 = (long)(t * 2 + 0) * NN * NN;
    long ob1 = (long)(t * 2 + 1) * NN * NN;
#pragma unroll
    for (int k = 0; k < 2; ++k) {
#pragma unroll
        for (int q = 0; q < 2; ++q) {
            int n = nt * 32 + ra + k * 16;
            int m = mt * 32 + cb + q * 16;
            float sim = __fdividef(acc[k][q], na[k] * nb[q] + 1e-6f);
            float v0 = fminf(fmaxf(sim, 0.0f), 1.0f);
            float v1 = fminf(fmaxf(1.0f - sim, 0.0f), 1.0f);
            out[ob0 + n * NN + m] = v0;
            out[ob1 + n * NN + m] = v1;
            if (mir) {
                out[ob0 + m * NN + n] = v0;
                out[ob1 + m * NN + n] = v1;
            }
        }
    }
}

// ---- layer-0 edge update + partial aggregation over a 64-j half ----
// grid (32, T, 2), block 128: 4 i-rows per block, z selects j-half
__global__ void __launch_bounds__(128) k_edge0(
        const float* __restrict__ node, const float* __restrict__ edge,
        const float* __restrict__ ew, const float* __restrict__ eb,
        float* __restrict__ stats) {
    int z = blockIdx.z;
    if (z == 0 && blockIdx.x == 0 && blockIdx.y == 0) {
        stats[threadIdx.x] = 0.0f; stats[threadIdx.x + 128] = 0.0f;
    }
    int t = blockIdx.y;
    int lane = threadIdx.x & 31, w = threadIdx.x >> 5;
    int i = blockIdx.x * 4 + w;
    int j0 = z * 64;
    float w0 = ew[0], w1 = ew[1], w2 = ew[2], b = eb[0];
    const float4* x4 = (const float4*)(node + t * NN * FF);
    float4 xi = x4[i * 32 + lane];
    float cx = fmaf(w0 + w1, xi.x, b), cy = fmaf(w0 + w1, xi.y, b);
    float cz = fmaf(w0 + w1, xi.z, b), cw_ = fmaf(w0 + w1, xi.w, b);
    const float4* e4 = (const float4*)(edge + ((size_t)(t * NN + i) * NN) * FF);
    float ax = 0.f, ay = 0.f, az = 0.f, aw = 0.f;
#pragma unroll 8
    for (int jj = 0; jj < 64; ++jj) {
        int j = j0 + jj;
        float4 e = __ldcs(&e4[j * 32 + lane]);
        float4 xj = x4[j * 32 + lane];
        ax += tanh_fast(fmaf(w2, e.x, fmaf(-w1, xj.x, cx)));
        ay += tanh_fast(fmaf(w2, e.y, fmaf(-w1, xj.y, cy)));
        az += tanh_fast(fmaf(w2, e.z, fmaf(-w1, xj.z, cz)));
        aw += tanh_fast(fmaf(w2, e.w, fmaf(-w1, xj.w, cw_)));
    }
    // subtract diagonal if i falls in this half
    if ((i >> 6) == z) {
        float4 eii = e4[i * 32 + lane];
        ax -= tanh_fast(fmaf(w2, eii.x, fmaf(-w1, xi.x, cx)));
        ay -= tanh_fast(fmaf(w2, eii.y, fmaf(-w1, xi.y, cy)));
        az -= tanh_fast(fmaf(w2, eii.z, fmaf(-w1, xi.z, cz)));
        aw -= tanh_fast(fmaf(w2, eii.w, fmaf(-w1, xi.w, cw_)));
    }
    float4 acc; acc.x = ax; acc.y = ay; acc.z = az; acc.w = aw;
    float* dst = (z == 0) ? g_aggrA : g_aggrB;
    ((float4*)(dst + (t * NN + i) * FF))[lane] = acc;
}

// ---- layer-1: recompute e0 on the fly, chain layer-1 tanh, partial-aggregate ----
__global__ void __launch_bounds__(128) k_edge1(
        const float* __restrict__ node0, const float* __restrict__ node1,
        const float* __restrict__ edge,
        const float* __restrict__ ew, const float* __restrict__ eb,
        float* __restrict__ stats) {
    int z = blockIdx.z;
    if (z == 0 && blockIdx.x == 0 && blockIdx.y == 0) {
        stats[threadIdx.x] = 0.0f; stats[threadIdx.x + 128] = 0.0f;
    }
    int t = blockIdx.y;
    int lane = threadIdx.x & 31, w = threadIdx.x >> 5;
    int i = blockIdx.x * 4 + w;
    int j0 = z * 64;
    float w00 = ew[0], w01 = ew[1], w02 = ew[2], b0 = eb[0];
    float w10 = ew[3], w11 = ew[4], w12 = ew[5], b1 = eb[1];
    const float4* x04 = (const float4*)(node0 + t * NN * FF);
    const float4* x14 = (const float4*)(node1 + t * NN * FF);
    float4 xi0 = x04[i * 32 + lane];
    float4 xi1 = x14[i * 32 + lane];
    float c0x = fmaf(w00 + w01, xi0.x, b0), c0y = fmaf(w00 + w01, xi0.y, b0);
    float c0z = fmaf(w00 + w01, xi0.z, b0), c0w = fmaf(w00 + w01, xi0.w, b0);
    float c1x = fmaf(w10 + w11, xi1.x, b1), c1y = fmaf(w10 + w11, xi1.y, b1);
    float c1z = fmaf(w10 + w11, xi1.z, b1), c1w = fmaf(w10 + w11, xi1.w, b1);
    const float4* e4 = (const float4*)(edge + ((size_t)(t * NN + i) * NN) * FF);
    float ax = 0.f, ay = 0.f, az = 0.f, aw = 0.f;
#pragma unroll 4
    for (int jj = 0; jj < 64; ++jj) {
        int j = j0 + jj;
        float4 e  = __ldcs(&e4[j * 32 + lane]);
        float4 x0 = x04[j * 32 + lane];
        float4 x1 = x14[j * 32 + lane];
        float e0x = tanh_fast(fmaf(w02, e.x, fmaf(-w01, x0.x, c0x)));
        float e0y = tanh_fast(fmaf(w02, e.y, fmaf(-w01, x0.y, c0y)));
        float e0z = tanh_fast(fmaf(w02, e.z, fmaf(-w01, x0.z, c0z)));
        float e0w = tanh_fast(fmaf(w02, e.w, fmaf(-w01, x0.w, c0w)));
        ax += tanh_fast(fmaf(w12, e0x, fmaf(-w11, x1.x, c1x)));
        ay += tanh_fast(fmaf(w12, e0y, fmaf(-w11, x1.y, c1y)));
        az += tanh_fast(fmaf(w12, e0z, fmaf(-w11, x1.z, c1z)));
        aw += tanh_fast(fmaf(w12, e0w, fmaf(-w11, x1.w, c1w)));
    }
    if ((i >> 6) == z) {
        float4 e = e4[i * 32 + lane];
        float e0x = tanh_fast(fmaf(w02, e.x, fmaf(-w01, xi0.x, c0x)));
        float e0y = tanh_fast(fmaf(w02, e.y, fmaf(-w01, xi0.y, c0y)));
        float e0z = tanh_fast(fmaf(w02, e.z, fmaf(-w01, xi0.z, c0z)));
        float e0w = tanh_fast(fmaf(w02, e.w, fmaf(-w01, xi0.w, c0w)));
        ax -= tanh_fast(fmaf(w12, e0x, fmaf(-w11, xi1.x, c1x)));
        ay -= tanh_fast(fmaf(w12, e0y, fmaf(-w11, xi1.y, c1y)));
        az -= tanh_fast(fmaf(w12, e0z, fmaf(-w11, xi1.z, c1z)));
        aw -= tanh_fast(fmaf(w12, e0w, fmaf(-w11, xi1.w, c1w)));
    }
    float4 acc; acc.x = ax; acc.y = ay; acc.z = az; acc.w = aw;
    float* dst = (z == 0) ? g_aggrA : g_aggrB;
    ((float4*)(dst + (t * NN + i) * FF))[lane] = acc;
}

// ---- node GEMM (all-float4 mainloop) + fused BN-stat accumulation ----
// grid T*8 (16-row tiles), 256 threads; dyn smem: Ws4[128][33] + hs4[16][33]
__global__ void __launch_bounds__(256) k_gemm(
        const float* __restrict__ x, const float* __restrict__ cw,
        const float* __restrict__ W, float* __restrict__ y, float* __restrict__ stats) {
    extern __shared__ float4 sm4[];
    float4* Ws = sm4;               // [g][k], pitch 33 float4
    float4* hs = sm4 + 128 * 33;    // [r][k], pitch 33 float4
    float c0 = cw[0], c1 = cw[1];
    int t = blockIdx.x >> 3;
    int r0 = (blockIdx.x & 7) * 16;
    int tid = threadIdx.x;
    const float4* W4 = (const float4*)W;
#pragma unroll
    for (int i = 0; i < 16; ++i) {
        int idx = tid + i * 256;
        int g = idx >> 5, k = idx & 31;
        Ws[g * 33 + k] = W4[idx];
    }
    const float4* x4 = (const float4*)(x + (t * NN + r0) * FF);
    const float4* a4 = (const float4*)(g_aggrA + (t * NN + r0) * FF);
    const float4* b4 = (const float4*)(g_aggrB + (t * NN + r0) * FF);
#pragma unroll
    for (int i = 0; i < 2; ++i) {
        int idx = tid + i * 256;
        int r = idx >> 5, k = idx & 31;
        float4 xv = x4[idx], av = a4[idx], bv = b4[idx], h;
        h.x = lrelu(fmaf(c1, av.x + bv.x, c0 * xv.x));
        h.y = lrelu(fmaf(c1, av.y + bv.y, c0 * xv.y));
        h.z = lrelu(fmaf(c1, av.z + bv.z, c0 * xv.z));
        h.w = lrelu(fmaf(c1, av.w + bv.w, c0 * xv.w));
        hs[r * 33 + k] = h;
    }
    __syncthreads();
    int rt = tid & 7, gt = tid >> 3;   // rows {rt, rt+8}, g's gt*4..+3
    float acc[2][4] = { {0.f,0.f,0.f,0.f}, {0.f,0.f,0.f,0.f} };
#pragma unroll 4
    for (int k = 0; k < 32; ++k) {
        float4 a0 = hs[rt * 33 + k];
        float4 a1 = hs[(rt + 8) * 33 + k];
#pragma unroll
        for (int q = 0; q < 4; ++q) {
            float4 wv = Ws[(gt * 4 + q) * 33 + k];
            acc[0][q] = dot4(a0, wv, acc[0][q]);
            acc[1][q] = dot4(a1, wv, acc[1][q]);
        }
    }
    float4 v0; v0.x = acc[0][0]; v0.y = acc[0][1]; v0.z = acc[0][2]; v0.w = acc[0][3];
    float4 v1; v1.x = acc[1][0]; v1.y = acc[1][1]; v1.z = acc[1][2]; v1.w = acc[1][3];
    *(float4*)(y + (t * NN + r0 + rt) * FF + gt * 4) = v0;
    *(float4*)(y + (t * NN + r0 + rt + 8) * FF + gt * 4) = v1;
#pragma unroll
    for (int q = 0; q < 4; ++q) {
        float s  = acc[0][q] + acc[1][q];
        float ss = fmaf(acc[0][q], acc[0][q], acc[1][q] * acc[1][q]);
#pragma unroll
        for (int o = 4; o; o >>= 1) {
            s  += __shfl_down_sync(0xffffffffu, s,  o, 8);
            ss += __shfl_down_sync(0xffffffffu, ss, o, 8);
        }
        if (rt == 0) {
            int g = gt * 4 + q;
            atomicAdd(&stats[g], s);
            atomicAdd(&stats[FF + g], ss);
        }
    }
}

// ---- BN-apply + LeakyReLU: grid 64, block 256, 4 independent float4 per thread ----
__global__ void __launch_bounds__(256) k_bnfuse(
        const float* __restrict__ y, const float* __restrict__ gamma,
        const float* __restrict__ beta, float* __restrict__ xout,
        const float* __restrict__ stats) {
    int tid = threadIdx.x;
    int f4 = tid & 31;
    const float inv = 1.0f / (float)TN;
    float4 smv = ((const float4*)stats)[f4];
    float4 sqv = ((const float4*)(stats + FF))[f4];
    float4 gv  = ((const float4*)gamma)[f4];
    float4 bv  = ((const float4*)beta)[f4];
    float mux = smv.x * inv, muy = smv.y * inv, muz = smv.z * inv, muw = smv.w * inv;
    float rx = rsqrtf(fmaf(-mux, mux, sqv.x * inv) + 1e-5f) * gv.x;
    float ry = rsqrtf(fmaf(-muy, muy, sqv.y * inv) + 1e-5f) * gv.y;
    float rz = rsqrtf(fmaf(-muz, muz, sqv.z * inv) + 1e-5f) * gv.z;
    float rw = rsqrtf(fmaf(-muw, muw, sqv.w * inv) + 1e-5f) * gv.w;
#pragma unroll
    for (int i = 0; i < 4; ++i) {
        int idx = blockIdx.x * 1024 + i * 256 + tid;
        float4 yv = ((const float4*)y)[idx];
        float4 o;
        o.x = lrelu(fmaf(yv.x - mux, rx, bv.x));
        o.y = lrelu(fmaf(yv.y - muy, ry, bv.y));
        o.z = lrelu(fmaf(yv.z - muz, rz, bv.z));
        o.w = lrelu(fmaf(yv.w - muw, rw, bv.w));
        ((float4*)xout)[idx] = o;
    }
}

extern "C" void kernel_launch(void* const* d_in, const int* in_sizes, int n_in,
                              void* d_out, int out_size) {
    const float* node  = (const float*)d_in[0];
    const float* edge  = (const float*)d_in[1];
    const float* ew    = (const float*)d_in[2];   // [L,3]
    const float* ebv   = (const float*)d_in[3];   // [L]
    const float* cw    = (const float*)d_in[4];   // [L,2]
    const float* nw    = (const float*)d_in[5];   // [L,F,F]
    const float* gamma = (const float*)d_in[6];   // [L,F]
    const float* beta  = (const float*)d_in[7];   // [L,F]
    float* out = (float*)d_out;

    void *p1, *p2, *py, *ps;
    cudaGetSymbolAddress(&p1, g_node1);
    cudaGetSymbolAddress(&p2, g_node2);
    cudaGetSymbolAddress(&py, g_y);
    cudaGetSymbolAddress(&ps, g_stats);
    float* node1 = (float*)p1;
    float* node2 = (float*)p2;
    float* y     = (float*)py;
    float* st    = (float*)ps;

    size_t gemm_smem = (size_t)(128 * 33 + 16 * 33) * sizeof(float4);
    cudaFuncSetAttribute(k_gemm, cudaFuncAttributeMaxDynamicSharedMemorySize, (int)gemm_smem);

    const int OUTBLK = TT * 2 * NN * NN;

    k_simcal<<<dim3(10, TT), 256>>>(node, out);

    // ---- layer 0 ----
    k_edge0<<<dim3(32, TT, 2), 128>>>(node, edge, ew, ebv, st);
    k_gemm<<<TT * 8, 256, gemm_smem>>>(node, cw, nw, y, st);
    k_bnfuse<<<64, 256>>>(y, gamma, beta, node1, st);
    k_simcal<<<dim3(10, TT), 256>>>(node1, out + OUTBLK);

    // ---- layer 1 (recompute layer-0 edges on the fly) ----
    k_edge1<<<dim3(32, TT, 2), 128>>>(node, node1, edge, ew, ebv, st + 2 * FF);
    k_gemm<<<TT * 8, 256, gemm_smem>>>(node1, cw + 2, nw + FF * FF, y, st + 2 * FF);
    k_bnfuse<<<64, 256>>>(y, gamma + FF, beta + FF, node2, st + 2 * FF);
    k_simcal<<<dim3(10, TT), 256>>>(node2, out + 2 * OUTBLK);
}

// round 12
// speedup vs baseline: 1.9307x; 1.0256x over previous
#include <cuda_runtime.h>
#include <math.h>

#define TT 16
#define NN 128
#define FF 128
#define TN (TT*NN)
#define SEG (TT*NN*FF)

// ---- scratch (__device__ globals; no allocation allowed) ----
__device__ float g_aggr[4*SEG];       // 4 j-quarter partial aggregates
__device__ float g_y[SEG];
__device__ float g_node1[SEG];
__device__ float g_node2[SEG];
__device__ float g_stats[4*FF];       // [sum0(128), sumsq0(128), sum1, sumsq1]

__device__ const int c_nt[10] = {0,0,0,0,1,1,1,2,2,3};
__device__ const int c_mt[10] = {0,1,2,3,1,2,3,2,3,3};

__device__ __forceinline__ float tanh_fast(float x) {
    float y; asm("tanh.approx.f32 %0, %1;" : "=f"(y) : "f"(x)); return y;
}
__device__ __forceinline__ float lrelu(float v) { return v >= 0.0f ? v : 0.01f * v; }
__device__ __forceinline__ float dot4(float4 a, float4 b, float acc) {
    return fmaf(a.x, b.x, fmaf(a.y, b.y, fmaf(a.z, b.z, fmaf(a.w, b.w, acc))));
}

// ---- sim_cal (+ optional fused BN-apply + node write-back) ----
// grid=(10 sym tiles, T), 256 threads.
// stats==nullptr: src is node feats, staged directly, no write-back.
// stats!=nullptr: src is pre-BN y; BN+lrelu applied during staging; diagonal
//                 tiles write normalized rows to xout (each row block exactly once).
__global__ void __launch_bounds__(256) k_simcal(
        const float* __restrict__ src, const float* __restrict__ stats,
        const float* __restrict__ gamma, const float* __restrict__ beta,
        float* __restrict__ xout, float* __restrict__ out) {
    __shared__ float4 As[32*33], Bs[32*33];
    __shared__ float nA[32], nB[32];
    __shared__ float4 sc4[32], sh4[32];
    int t = blockIdx.y;
    int nt = c_nt[blockIdx.x], mt = c_mt[blockIdx.x];
    int tid = threadIdx.x;
    bool bn = (stats != nullptr);
    if (bn && tid < 32) {
        const float inv = 1.0f / (float)TN;
        float4 sm = ((const float4*)stats)[tid];
        float4 sq = ((const float4*)(stats + FF))[tid];
        float4 gv = ((const float4*)gamma)[tid];
        float4 bv = ((const float4*)beta)[tid];
        float4 sc, sh;
        float mu = sm.x * inv; sc.x = rsqrtf(fmaf(-mu, mu, sq.x * inv) + 1e-5f) * gv.x; sh.x = fmaf(-mu, sc.x, bv.x);
        mu = sm.y * inv;       sc.y = rsqrtf(fmaf(-mu, mu, sq.y * inv) + 1e-5f) * gv.y; sh.y = fmaf(-mu, sc.y, bv.y);
        mu = sm.z * inv;       sc.z = rsqrtf(fmaf(-mu, mu, sq.z * inv) + 1e-5f) * gv.z; sh.z = fmaf(-mu, sc.z, bv.z);
        mu = sm.w * inv;       sc.w = rsqrtf(fmaf(-mu, mu, sq.w * inv) + 1e-5f) * gv.w; sh.w = fmaf(-mu, sc.w, bv.w);
        sc4[tid] = sc; sh4[tid] = sh;
    }
    __syncthreads();
    const float4* xa = (const float4*)(src + (t * NN + nt * 32) * FF);
    const float4* xb = (const float4*)(src + (t * NN + mt * 32) * FF);
#pragma unroll
    for (int i = 0; i < 4; ++i) {
        int idx = tid + i * 256;
        int r = idx >> 5, k = idx & 31;
        float4 a = xa[idx], b = xb[idx];
        if (bn) {
            float4 sc = sc4[k], sh = sh4[k];
            a.x = lrelu(fmaf(a.x, sc.x, sh.x)); a.y = lrelu(fmaf(a.y, sc.y, sh.y));
            a.z = lrelu(fmaf(a.z, sc.z, sh.z)); a.w = lrelu(fmaf(a.w, sc.w, sh.w));
            b.x = lrelu(fmaf(b.x, sc.x, sh.x)); b.y = lrelu(fmaf(b.y, sc.y, sh.y));
            b.z = lrelu(fmaf(b.z, sc.z, sh.z)); b.w = lrelu(fmaf(b.w, sc.w, sh.w));
        }
        As[r * 33 + k] = a;
        Bs[r * 33 + k] = b;
    }
    __syncthreads();
    if (tid < 64) {
        int r = tid & 31;
        const float4* s4 = (tid < 32) ? As : Bs;
        float s = 0.f;
#pragma unroll 8
        for (int k = 0; k < 32; ++k) { float4 v = s4[r * 33 + k]; s = dot4(v, v, s); }
        if (tid < 32) nA[r] = sqrtf(s); else nB[r] = sqrtf(s);
    }
    int ra = tid & 15, cb = tid >> 4;     // rows {ra, ra+16}, cols {cb, cb+16}
    float a00 = 0.f, a01 = 0.f, a10 = 0.f, a11 = 0.f;
#pragma unroll 8
    for (int k = 0; k < 32; ++k) {
        float4 r0 = As[ra * 33 + k], r1 = As[(ra + 16) * 33 + k];
        float4 q0 = Bs[cb * 33 + k], q1 = Bs[(cb + 16) * 33 + k];
        a00 = dot4(r0, q0, a00); a01 = dot4(r0, q1, a01);
        a10 = dot4(r1, q0, a10); a11 = dot4(r1, q1, a11);
    }
    __syncthreads();
    float na[2] = { nA[ra], nA[ra + 16] };
    float nb[2] = { nB[cb], nB[cb + 16] };
    float acc[2][2] = { {a00, a01}, {a10, a11} };
    bool mir = (nt != mt);
    long ob0 = (long)(t * 2 + 0) * NN * NN;
    long ob1 = (long)(t * 2 + 1) * NN * NN;
#pragma unroll
    for (int k = 0; k < 2; ++k) {
#pragma unroll
        for (int q = 0; q < 2; ++q) {
            int n = nt * 32 + ra + k * 16;
            int m = mt * 32 + cb + q * 16;
            float sim = __fdividef(acc[k][q], na[k] * nb[q] + 1e-6f);
            float v0 = fminf(fmaxf(sim, 0.0f), 1.0f);
            float v1 = fminf(fmaxf(1.0f - sim, 0.0f), 1.0f);
            out[ob0 + n * NN + m] = v0;
            out[ob1 + n * NN + m] = v1;
            if (mir) {
                out[ob0 + m * NN + n] = v0;
                out[ob1 + m * NN + n] = v1;
            }
        }
    }
    // diagonal tiles write the BN'd rows back (each row block exactly once)
    if (bn && nt == mt) {
        float4* xo = (float4*)(xout + (t * NN + nt * 32) * FF);
#pragma unroll
        for (int i = 0; i < 4; ++i) {
            int idx = tid + i * 256;
            int r = idx >> 5, k = idx & 31;
            xo[idx] = As[r * 33 + k];
        }
    }
}

// ---- layer-0 edge update + partial aggregation over a 32-j quarter ----
// grid (32, T, 4), block 128: 4 i-rows per block, z selects j-quarter
__global__ void __launch_bounds__(128) k_edge0(
        const float* __restrict__ node, const float* __restrict__ edge,
        const float* __restrict__ ew, const float* __restrict__ eb,
        float* __restrict__ stats) {
    int z = blockIdx.z;
    if (z == 0 && blockIdx.x == 0 && blockIdx.y == 0) {
        stats[threadIdx.x] = 0.0f; stats[threadIdx.x + 128] = 0.0f;
    }
    int t = blockIdx.y;
    int lane = threadIdx.x & 31, w = threadIdx.x >> 5;
    int i = blockIdx.x * 4 + w;
    int j0 = z * 32;
    float w0 = ew[0], w1 = ew[1], w2 = ew[2], b = eb[0];
    const float4* x4 = (const float4*)(node + t * NN * FF);
    float4 xi = x4[i * 32 + lane];
    float cx = fmaf(w0 + w1, xi.x, b), cy = fmaf(w0 + w1, xi.y, b);
    float cz = fmaf(w0 + w1, xi.z, b), cw_ = fmaf(w0 + w1, xi.w, b);
    const float4* e4 = (const float4*)(edge + ((size_t)(t * NN + i) * NN) * FF);
    float ax = 0.f, ay = 0.f, az = 0.f, aw = 0.f;
#pragma unroll 8
    for (int jj = 0; jj < 32; ++jj) {
        int j = j0 + jj;
        float4 e = __ldcs(&e4[j * 32 + lane]);
        float4 xj = x4[j * 32 + lane];
        ax += tanh_fast(fmaf(w2, e.x, fmaf(-w1, xj.x, cx)));
        ay += tanh_fast(fmaf(w2, e.y, fmaf(-w1, xj.y, cy)));
        az += tanh_fast(fmaf(w2, e.z, fmaf(-w1, xj.z, cz)));
        aw += tanh_fast(fmaf(w2, e.w, fmaf(-w1, xj.w, cw_)));
    }
    if ((i >> 5) == z) {   // subtract diagonal if i falls in this quarter
        float4 eii = e4[i * 32 + lane];
        ax -= tanh_fast(fmaf(w2, eii.x, fmaf(-w1, xi.x, cx)));
        ay -= tanh_fast(fmaf(w2, eii.y, fmaf(-w1, xi.y, cy)));
        az -= tanh_fast(fmaf(w2, eii.z, fmaf(-w1, xi.z, cz)));
        aw -= tanh_fast(fmaf(w2, eii.w, fmaf(-w1, xi.w, cw_)));
    }
    float4 acc; acc.x = ax; acc.y = ay; acc.z = az; acc.w = aw;
    ((float4*)(g_aggr + z * SEG + (t * NN + i) * FF))[lane] = acc;
}

// ---- layer-1: recompute e0 on the fly, chain layer-1 tanh, partial-aggregate ----
__global__ void __launch_bounds__(128) k_edge1(
        const float* __restrict__ node0, const float* __restrict__ node1,
        const float* __restrict__ edge,
        const float* __restrict__ ew, const float* __restrict__ eb,
        float* __restrict__ stats) {
    int z = blockIdx.z;
    if (z == 0 && blockIdx.x == 0 && blockIdx.y == 0) {
        stats[threadIdx.x] = 0.0f; stats[threadIdx.x + 128] = 0.0f;
    }
    int t = blockIdx.y;
    int lane = threadIdx.x & 31, w = threadIdx.x >> 5;
    int i = blockIdx.x * 4 + w;
    int j0 = z * 32;
    float w00 = ew[0], w01 = ew[1], w02 = ew[2], b0 = eb[0];
    float w10 = ew[3], w11 = ew[4], w12 = ew[5], b1 = eb[1];
    const float4* x04 = (const float4*)(node0 + t * NN * FF);
    const float4* x14 = (const float4*)(node1 + t * NN * FF);
    float4 xi0 = x04[i * 32 + lane];
    float4 xi1 = x14[i * 32 + lane];
    float c0x = fmaf(w00 + w01, xi0.x, b0), c0y = fmaf(w00 + w01, xi0.y, b0);
    float c0z = fmaf(w00 + w01, xi0.z, b0), c0w = fmaf(w00 + w01, xi0.w, b0);
    float c1x = fmaf(w10 + w11, xi1.x, b1), c1y = fmaf(w10 + w11, xi1.y, b1);
    float c1z = fmaf(w10 + w11, xi1.z, b1), c1w = fmaf(w10 + w11, xi1.w, b1);
    const float4* e4 = (const float4*)(edge + ((size_t)(t * NN + i) * NN) * FF);
    float ax = 0.f, ay = 0.f, az = 0.f, aw = 0.f;
#pragma unroll 4
    for (int jj = 0; jj < 32; ++jj) {
        int j = j0 + jj;
        float4 e  = __ldcs(&e4[j * 32 + lane]);
        float4 x0 = x04[j * 32 + lane];
        float4 x1 = x14[j * 32 + lane];
        float e0x = tanh_fast(fmaf(w02, e.x, fmaf(-w01, x0.x, c0x)));
        float e0y = tanh_fast(fmaf(w02, e.y, fmaf(-w01, x0.y, c0y)));
        float e0z = tanh_fast(fmaf(w02, e.z, fmaf(-w01, x0.z, c0z)));
        float e0w = tanh_fast(fmaf(w02, e.w, fmaf(-w01, x0.w, c0w)));
        ax += tanh_fast(fmaf(w12, e0x, fmaf(-w11, x1.x, c1x)));
        ay += tanh_fast(fmaf(w12, e0y, fmaf(-w11, x1.y, c1y)));
        az += tanh_fast(fmaf(w12, e0z, fmaf(-w11, x1.z, c1z)));
        aw += tanh_fast(fmaf(w12, e0w, fmaf(-w11, x1.w, c1w)));
    }
    if ((i >> 5) == z) {
        float4 e = e4[i * 32 + lane];
        float e0x = tanh_fast(fmaf(w02, e.x, fmaf(-w01, xi0.x, c0x)));
        float e0y = tanh_fast(fmaf(w02, e.y, fmaf(-w01, xi0.y, c0y)));
        float e0z = tanh_fast(fmaf(w02, e.z, fmaf(-w01, xi0.z, c0z)));
        float e0w = tanh_fast(fmaf(w02, e.w, fmaf(-w01, xi0.w, c0w)));
        ax -= tanh_fast(fmaf(w12, e0x, fmaf(-w11, xi1.x, c1x)));
        ay -= tanh_fast(fmaf(w12, e0y, fmaf(-w11, xi1.y, c1y)));
        az -= tanh_fast(fmaf(w12, e0z, fmaf(-w11, xi1.z, c1z)));
        aw -= tanh_fast(fmaf(w12, e0w, fmaf(-w11, xi1.w, c1w)));
    }
    float4 acc; acc.x = ax; acc.y = ay; acc.z = az; acc.w = aw;
    ((float4*)(g_aggr + z * SEG + (t * NN + i) * FF))[lane] = acc;
}

// ---- node GEMM (all-float4 mainloop) + fused BN-stat accumulation ----
// grid T*8 (16-row tiles), 256 threads; dyn smem: Ws4[128][33] + hs4[16][33]
__global__ void __launch_bounds__(256) k_gemm(
        const float* __restrict__ x, const float* __restrict__ cw,
        const float* __restrict__ W, float* __restrict__ y, float* __restrict__ stats) {
    extern __shared__ float4 sm4[];
    float4* Ws = sm4;               // [g][k], pitch 33 float4
    float4* hs = sm4 + 128 * 33;    // [r][k], pitch 33 float4
    float c0 = cw[0], c1 = cw[1];
    int t = blockIdx.x >> 3;
    int r0 = (blockIdx.x & 7) * 16;
    int tid = threadIdx.x;
    const float4* W4 = (const float4*)W;
#pragma unroll
    for (int i = 0; i < 16; ++i) {
        int idx = tid + i * 256;
        int g = idx >> 5, k = idx & 31;
        Ws[g * 33 + k] = W4[idx];
    }
    const float4* x4 = (const float4*)(x + (t * NN + r0) * FF);
    const float4* a4 = (const float4*)(g_aggr + 0 * SEG + (t * NN + r0) * FF);
    const float4* b4 = (const float4*)(g_aggr + 1 * SEG + (t * NN + r0) * FF);
    const float4* c4 = (const float4*)(g_aggr + 2 * SEG + (t * NN + r0) * FF);
    const float4* d4 = (const float4*)(g_aggr + 3 * SEG + (t * NN + r0) * FF);
#pragma unroll
    for (int i = 0; i < 2; ++i) {
        int idx = tid + i * 256;
        int r = idx >> 5, k = idx & 31;
        float4 xv = x4[idx], av = a4[idx], bv = b4[idx], cv = c4[idx], dv = d4[idx], h;
        h.x = lrelu(fmaf(c1, (av.x + bv.x) + (cv.x + dv.x), c0 * xv.x));
        h.y = lrelu(fmaf(c1, (av.y + bv.y) + (cv.y + dv.y), c0 * xv.y));
        h.z = lrelu(fmaf(c1, (av.z + bv.z) + (cv.z + dv.z), c0 * xv.z));
        h.w = lrelu(fmaf(c1, (av.w + bv.w) + (cv.w + dv.w), c0 * xv.w));
        hs[r * 33 + k] = h;
    }
    __syncthreads();
    int rt = tid & 7, gt = tid >> 3;   // rows {rt, rt+8}, g's gt*4..+3
    float acc[2][4] = { {0.f,0.f,0.f,0.f}, {0.f,0.f,0.f,0.f} };
#pragma unroll 4
    for (int k = 0; k < 32; ++k) {
        float4 a0 = hs[rt * 33 + k];
        float4 a1 = hs[(rt + 8) * 33 + k];
#pragma unroll
        for (int q = 0; q < 4; ++q) {
            float4 wv = Ws[(gt * 4 + q) * 33 + k];
            acc[0][q] = dot4(a0, wv, acc[0][q]);
            acc[1][q] = dot4(a1, wv, acc[1][q]);
        }
    }
    float4 v0; v0.x = acc[0][0]; v0.y = acc[0][1]; v0.z = acc[0][2]; v0.w = acc[0][3];
    float4 v1; v1.x = acc[1][0]; v1.y = acc[1][1]; v1.z = acc[1][2]; v1.w = acc[1][3];
    *(float4*)(y + (t * NN + r0 + rt) * FF + gt * 4) = v0;
    *(float4*)(y + (t * NN + r0 + rt + 8) * FF + gt * 4) = v1;
#pragma unroll
    for (int q = 0; q < 4; ++q) {
        float s  = acc[0][q] + acc[1][q];
        float ss = fmaf(acc[0][q], acc[0][q], acc[1][q] * acc[1][q]);
#pragma unroll
        for (int o = 4; o; o >>= 1) {
            s  += __shfl_down_sync(0xffffffffu, s,  o, 8);
            ss += __shfl_down_sync(0xffffffffu, ss, o, 8);
        }
        if (rt == 0) {
            int g = gt * 4 + q;
            atomicAdd(&stats[g], s);
            atomicAdd(&stats[FF + g], ss);
        }
    }
}

extern "C" void kernel_launch(void* const* d_in, const int* in_sizes, int n_in,
                              void* d_out, int out_size) {
    const float* node  = (const float*)d_in[0];
    const float* edge  = (const float*)d_in[1];
    const float* ew    = (const float*)d_in[2];   // [L,3]
    const float* ebv   = (const float*)d_in[3];   // [L]
    const float* cw    = (const float*)d_in[4];   // [L,2]
    const float* nw    = (const float*)d_in[5];   // [L,F,F]
    const float* gamma = (const float*)d_in[6];   // [L,F]
    const float* beta  = (const float*)d_in[7];   // [L,F]
    float* out = (float*)d_out;

    void *p1, *p2, *py, *ps;
    cudaGetSymbolAddress(&p1, g_node1);
    cudaGetSymbolAddress(&p2, g_node2);
    cudaGetSymbolAddress(&py, g_y);
    cudaGetSymbolAddress(&ps, g_stats);
    float* node1 = (float*)p1;
    float* node2 = (float*)p2;
    float* y     = (float*)py;
    float* st    = (float*)ps;

    size_t gemm_smem = (size_t)(128 * 33 + 16 * 33) * sizeof(float4);
    cudaFuncSetAttribute(k_gemm, cudaFuncAttributeMaxDynamicSharedMemorySize, (int)gemm_smem);

    const int OUTBLK = TT * 2 * NN * NN;

    // sim_cal on input features (no BN)
    k_simcal<<<dim3(10, TT), 256>>>(node, nullptr, nullptr, nullptr, nullptr, out);

    // ---- layer 0 ----
    k_edge0<<<dim3(32, TT, 4), 128>>>(node, edge, ew, ebv, st);
    k_gemm<<<TT * 8, 256, gemm_smem>>>(node, cw, nw, y, st);
    // BN-apply fused into simcal; diagonal tiles write node1
    k_simcal<<<dim3(10, TT), 256>>>(y, st, gamma, beta, node1, out + OUTBLK);

    // ---- layer 1 (recompute layer-0 edges on the fly) ----
    k_edge1<<<dim3(32, TT, 4), 128>>>(node, node1, edge, ew, ebv, st + 2 * FF);
    k_gemm<<<TT * 8, 256, gemm_smem>>>(node1, cw + 2, nw + FF * FF, y, st + 2 * FF);
    k_simcal<<<dim3(10, TT), 256>>>(y, st + 2 * FF, gamma + FF, beta + FF, node2,
                                    out + 2 * OUTBLK);
}